// round 13
// baseline (speedup 1.0000x reference)
#include <cuda_runtime.h>
#include <cuda_bf16.h>
#include <cstdint>

#define BB 16
#define SS 2048
#define DD 1024
#define HH 1024
#define RR 16
#define MTOT (BB*SS)   // 32768
#define NN2 2048       // Wa||Wu stacked rows

#if defined(__CUDA_ARCH_FEAT_SM103_ALL) || defined(__CUDA_ARCH_FEAT_SM100_ALL)
#define HAS_TCGEN05 1
#elif defined(__CUDA_ARCH_SPECIFIC__)
#if (__CUDA_ARCH_SPECIFIC__ == 1030) || (__CUDA_ARCH_SPECIFIC__ == 1000)
#define HAS_TCGEN05 1
#else
#define HAS_TCGEN05 0
#endif
#else
#define HAS_TCGEN05 0
#endif

// Scratch
__device__ float A_buf[(size_t)BB*SS*HH];
__device__ float U_buf[(size_t)BB*SS*HH];
__device__ float G_buf[(size_t)BB*SS*RR];

__device__ __align__(16) __nv_bfloat16 Xhi[(size_t)MTOT*DD];
__device__ __align__(16) __nv_bfloat16 Xlo[(size_t)MTOT*DD];
__device__ __align__(16) __nv_bfloat16 Whi[(size_t)NN2*DD];
__device__ __align__(16) __nv_bfloat16 Wlo[(size_t)NN2*DD];

// ============================ helpers ============================
__device__ __forceinline__ uint32_t smem_u32(const void* p) {
    uint32_t a;
    asm("{ .reg .u64 t; cvta.to.shared.u64 t, %1; cvt.u32.u64 %0, t; }" : "=r"(a) : "l"(p));
    return a;
}
#define SWZ128(o) ((o) ^ (((o) >> 3) & 0x70))

__device__ __forceinline__ uint32_t pack_bf16x2(float lo, float hi) {
    uint32_t r;
    asm("cvt.rn.bf16x2.f32 %0, %1, %2;" : "=r"(r) : "f"(hi), "f"(lo));
    return r;
}

// packed fp32x2 helpers (HW FFMA2 on sm_100+/sm_103; scalar fallback for base pass)
__device__ __forceinline__ uint64_t pk_f32x2(float lo, float hi) {
    return ((uint64_t)__float_as_uint(hi) << 32) | (uint64_t)__float_as_uint(lo);
}
__device__ __forceinline__ float pk_lo(uint64_t p) { return __uint_as_float((uint32_t)p); }
__device__ __forceinline__ float pk_hi(uint64_t p) { return __uint_as_float((uint32_t)(p >> 32)); }

#if HAS_TCGEN05
__device__ __forceinline__ uint64_t fma2(uint64_t a, uint64_t b, uint64_t c) {
    uint64_t d;
    asm("fma.rn.f32x2 %0, %1, %2, %3;" : "=l"(d) : "l"(a), "l"(b), "l"(c));
    return d;
}
#else
__device__ __forceinline__ uint64_t fma2(uint64_t a, uint64_t b, uint64_t c) {
    return pk_f32x2(fmaf(pk_lo(a), pk_lo(b), pk_lo(c)),
                    fmaf(pk_hi(a), pk_hi(b), pk_hi(c)));
}
#endif

#if HAS_TCGEN05

__device__ __forceinline__ uint32_t elect_one() {
    uint32_t r;
    asm volatile("{ .reg .pred p; elect.sync _|p, 0xFFFFFFFF; selp.b32 %0, 1, 0, p; }" : "=r"(r));
    return r;
}

#define TC_ALLOC(smem_addr, ncols) \
    asm volatile("tcgen05.alloc.cta_group::1.sync.aligned.shared::cta.b32 [%0], %1;" \
                 :: "r"(smem_addr), "r"(ncols) : "memory")
#define TC_DEALLOC(tmem, ncols) \
    asm volatile("tcgen05.dealloc.cta_group::1.sync.aligned.b32 %0, %1;" :: "r"(tmem), "r"(ncols))
#define TC_COMMIT(mbar) \
    asm volatile("tcgen05.commit.cta_group::1.mbarrier::arrive::one.shared::cluster.b64 [%0];" \
                 :: "r"(mbar) : "memory")
#define TC_FENCE_AFTER()  asm volatile("tcgen05.fence::after_thread_sync;" ::: "memory")
#define TC_WAIT_LD()      asm volatile("tcgen05.wait::ld.sync.aligned;" ::: "memory")
#define FENCE_ASYNC_SHARED() asm volatile("fence.proxy.async.shared::cta;" ::: "memory")

#define CP_ASYNC16(dst, src) \
    asm volatile("cp.async.cg.shared.global [%0], [%1], 16;" :: "r"(dst), "l"(src) : "memory")
#define CP_COMMIT()  asm volatile("cp.async.commit_group;" ::: "memory")
#define CP_WAIT(n)   asm volatile("cp.async.wait_group %0;" :: "n"(n) : "memory")

#define MBAR_INIT(addr, cnt) \
    asm volatile("mbarrier.init.shared.b64 [%0], %1;" :: "r"(addr), "r"(cnt) : "memory")

#define MBAR_WAIT_PARITY(addr, parity) do { \
    uint32_t _mbar = (uint32_t)(addr); \
    uint32_t _par  = (uint32_t)(parity); \
    uint32_t _done; \
    asm volatile("{\n\t.reg .pred p;\n\t" \
        "mbarrier.try_wait.parity.acquire.cta.shared::cta.b64 p, [%1], %2;\n\t" \
        "selp.b32 %0, 1, 0, p;\n\t}" \
        : "=r"(_done) : "r"(_mbar), "r"(_par) : "memory"); \
    if (!_done) { \
        asm volatile("{\n\t.reg .pred P1;\n\t" \
            "WAIT_LOOP_%=:\n\t" \
            "mbarrier.try_wait.parity.acquire.cta.shared::cta.b64 P1, [%0], %1, 0x989680;\n\t" \
            "@P1 bra.uni WAIT_DONE_%=;\n\t" \
            "bra.uni WAIT_LOOP_%=;\n\t" \
            "WAIT_DONE_%=:\n\t}" \
            :: "r"(_mbar), "r"(_par) : "memory"); \
    } \
} while (0)

#define TC_LD_32X32B_X32(r, tmem_addr) \
    asm volatile( \
        "tcgen05.ld.sync.aligned.32x32b.x32.b32 " \
        "{%0, %1, %2, %3, %4, %5, %6, %7, " \
        " %8, %9, %10, %11, %12, %13, %14, %15, " \
        " %16, %17, %18, %19, %20, %21, %22, %23, " \
        " %24, %25, %26, %27, %28, %29, %30, %31}, [%32];" \
        : "=r"((r)[0]),  "=r"((r)[1]),  "=r"((r)[2]),  "=r"((r)[3]), \
          "=r"((r)[4]),  "=r"((r)[5]),  "=r"((r)[6]),  "=r"((r)[7]), \
          "=r"((r)[8]),  "=r"((r)[9]),  "=r"((r)[10]), "=r"((r)[11]), \
          "=r"((r)[12]), "=r"((r)[13]), "=r"((r)[14]), "=r"((r)[15]), \
          "=r"((r)[16]), "=r"((r)[17]), "=r"((r)[18]), "=r"((r)[19]), \
          "=r"((r)[20]), "=r"((r)[21]), "=r"((r)[22]), "=r"((r)[23]), \
          "=r"((r)[24]), "=r"((r)[25]), "=r"((r)[26]), "=r"((r)[27]), \
          "=r"((r)[28]), "=r"((r)[29]), "=r"((r)[30]), "=r"((r)[31]) \
        : "r"(tmem_addr))

// SW128 K-major smem descriptor (layout=2, version=1, SBO=64, LBO=1)
__device__ __forceinline__ uint64_t make_desc_sw128(uint32_t addr) {
    const uint64_t base = (uint64_t(2) << 61) | (uint64_t(1) << 46)
                        | (uint64_t(64) << 32) | (uint64_t(1) << 16);
    return base | ((uint64_t)(addr >> 4) & 0x3FFF);
}

__device__ __forceinline__ void mma_f16_ss(uint32_t d, uint64_t ad, uint64_t bd,
                                           uint32_t idesc, uint32_t en) {
    asm volatile(
        "{\n\t.reg .pred p;\n\t"
        "setp.ne.u32 p, %4, 0;\n\t"
        "tcgen05.mma.cta_group::1.kind::f16 [%0], %1, %2, %3, {%5,%5,%5,%5}, p;\n\t}"
        :: "r"(d), "l"(ad), "l"(bd), "r"(idesc), "r"(en), "r"(0u) : "memory");
}

#endif // HAS_TCGEN05

// ============================================================================
// Kernel 0: merged fp32 -> split-bf16 convert (X and W in one launch)
// ============================================================================
#define XBLKS ((MTOT * (DD/4)) / 256)   // 32768
#define WBLKS ((NN2  * (DD/4)) / 256)   // 2048

__global__ __launch_bounds__(256)
void convert_all_kernel(const float* __restrict__ x,
                        const float* __restrict__ Wa, const float* __restrict__ Wu)
{
    const float* src;
    __nv_bfloat16 *dhi, *dlo;
    size_t idx;
    if (blockIdx.x < XBLKS) {
        idx = (size_t)blockIdx.x * 256 + threadIdx.x;
        src = x + idx * 4;
        dhi = Xhi; dlo = Xlo;
    } else {
        idx = (size_t)(blockIdx.x - XBLKS) * 256 + threadIdx.x;
        size_t row = idx >> 8, col4 = idx & 255;
        src = (row < HH) ? (Wa + row * DD + col4 * 4) : (Wu + (row - HH) * DD + col4 * 4);
        dhi = Whi; dlo = Wlo;
    }
    float4 p = __ldg((const float4*)src);
    uint32_t w0 = __float_as_uint(p.x), w1 = __float_as_uint(p.y);
    uint32_t w2 = __float_as_uint(p.z), w3 = __float_as_uint(p.w);
    uint32_t h01 = __byte_perm(w0, w1, 0x7632);
    uint32_t h23 = __byte_perm(w2, w3, 0x7632);
    float l0 = p.x - __uint_as_float(w0 & 0xFFFF0000u);
    float l1 = p.y - __uint_as_float(w1 & 0xFFFF0000u);
    float l2 = p.z - __uint_as_float(w2 & 0xFFFF0000u);
    float l3 = p.w - __uint_as_float(w3 & 0xFFFF0000u);
    *(uint2*)(dhi + idx * 4) = make_uint2(h01, h23);
    *(uint2*)(dlo + idx * 4) = make_uint2(pack_bf16x2(l0, l1), pack_bf16x2(l2, l3));
}

// ============================================================================
// Kernel 1: tcgen05 split-bf16 projection GEMM (R6 known-good: 2-stage, KC=64)
// ============================================================================
#define TM 128
#define TN 256
#define KC 64
#define NCHUNK (DD / KC)     // 16

#define A_HI_OFF 0
#define A_LO_OFF 16384
#define B_HI_OFF 32768
#define B_LO_OFF 65536
#define STAGE_BYTES 98304
#define STAGE_BASE  1024
#define SMEM_TOTAL  (STAGE_BASE + 2 * STAGE_BYTES)   // 197632

__global__ __launch_bounds__(256, 1)
void proj_gemm_tc(const float* __restrict__ ba, const float* __restrict__ bu)
{
#if HAS_TCGEN05
    extern __shared__ char smem[];
    const uint32_t smb = smem_u32(smem);

    const uint32_t IDESC =
        (1u << 4) | (1u << 7) | (1u << 10) | ((TN / 8) << 17) | ((TM / 16) << 24);

    const int tid  = threadIdx.x;
    const int wid  = tid >> 5;
    const int lane = tid & 31;

    const int n0 = blockIdx.x * TN;
    const int m0 = blockIdx.y * TM;
    const bool isA = (n0 < HH);
    const int ncol0 = isA ? n0 : (n0 - HH);
    const float* bias = (isA ? ba : bu) + ncol0;
    float* outb = isA ? A_buf : U_buf;

    if (wid == 0) TC_ALLOC(smb + 0, 256);
    if (tid == 0) {
        MBAR_INIT(smb + 8, 1);
        MBAR_INIT(smb + 16, 1);
    }
    __syncthreads();
    uint32_t tmem_base;
    asm volatile("ld.shared.b32 %0, [%1];" : "=r"(tmem_base) : "r"(smb + 0));

    const uint32_t mb[2] = { smb + 8, smb + 16 };
    uint32_t ph[2] = { 0, 0 };

    for (int c = 0; c < NCHUNK; ++c) {
        const int st = c & 1;
        const uint32_t sb = smb + STAGE_BASE + st * STAGE_BYTES;
        const int kc0 = c * KC;

        if (c >= 2) { MBAR_WAIT_PARITY(mb[st], ph[st]); ph[st] ^= 1; }

        // A tiles: 128 rows x 64 bf16 (hi & lo)
        {
            const uint32_t aHi = sb + A_HI_OFF, aLo = sb + A_LO_OFF;
#pragma unroll
            for (int j = 0; j < 4; j++) {
                int u = tid + j * 256;              // 0..1023
                int row = u >> 3, cb = u & 7;
                uint32_t off = SWZ128((uint32_t)(row * 128 + cb * 16));
                const char* sH = (const char*)(Xhi + (size_t)(m0 + row) * DD + kc0) + cb * 16;
                const char* sL = (const char*)(Xlo + (size_t)(m0 + row) * DD + kc0) + cb * 16;
                CP_ASYNC16(aHi + off, sH);
                CP_ASYNC16(aLo + off, sL);
            }
        }
        // B tiles: 256 rows x 64 bf16 (hi & lo)
        {
            const uint32_t bHi = sb + B_HI_OFF, bLo = sb + B_LO_OFF;
#pragma unroll
            for (int j = 0; j < 8; j++) {
                int u = tid + j * 256;              // 0..2047
                int row = u >> 3, cb = u & 7;
                uint32_t off = SWZ128((uint32_t)(row * 128 + cb * 16));
                const char* sH = (const char*)(Whi + (size_t)(n0 + row) * DD + kc0) + cb * 16;
                const char* sL = (const char*)(Wlo + (size_t)(n0 + row) * DD + kc0) + cb * 16;
                CP_ASYNC16(bHi + off, sH);
                CP_ASYNC16(bLo + off, sL);
            }
        }
        CP_COMMIT();
        CP_WAIT(0);
        __syncthreads();

        if (wid == 0) {
            FENCE_ASYNC_SHARED();
            if (elect_one()) {
                uint64_t dAhi = make_desc_sw128(sb + A_HI_OFF);
                uint64_t dAlo = make_desc_sw128(sb + A_LO_OFF);
                uint64_t dBhi = make_desc_sw128(sb + B_HI_OFF);
                uint64_t dBlo = make_desc_sw128(sb + B_LO_OFF);
#pragma unroll
                for (int k = 0; k < 4; k++) {
                    uint32_t en0 = (c > 0 || k > 0) ? 1u : 0u;
                    mma_f16_ss(tmem_base, dAhi + k * 2, dBhi + k * 2, IDESC, en0);
                    mma_f16_ss(tmem_base, dAhi + k * 2, dBlo + k * 2, IDESC, 1u);
                    mma_f16_ss(tmem_base, dAlo + k * 2, dBhi + k * 2, IDESC, 1u);
                }
                TC_COMMIT(mb[st]);
            }
        }
    }

    MBAR_WAIT_PARITY(mb[0], ph[0]);
    MBAR_WAIT_PARITY(mb[1], ph[1]);
    TC_FENCE_AFTER();
    __syncthreads();

    // epilogue
    float* stg = (float*)(smem + STAGE_BASE);
    const int half = wid >> 2;
    const int subw = wid & 3;
    const int rowl = subw * 32 + lane;

    for (int slab = 0; slab < 4; ++slab) {
        const int c0 = slab * 64;
        uint32_t regs[32];
        TC_LD_32X32B_X32(regs, tmem_base + c0 + half * 32);
        TC_WAIT_LD();
#pragma unroll
        for (int j = 0; j < 32; j++) {
            int n = c0 + half * 32 + j;
            float val = __uint_as_float(regs[j]) + __ldg(&bias[n]);
            if (isA) val = 1.f / (1.f + __expf(-val));
            stg[rowl * 65 + half * 32 + j] = val;
        }
        __syncthreads();
#pragma unroll
        for (int i = 0; i < 8; i++) {
            int idx = tid + i * 256;
            int row = idx >> 4, c4 = idx & 15;
            const float* src = &stg[row * 65 + c4 * 4];
            float4 vv;
            vv.x = src[0]; vv.y = src[1]; vv.z = src[2]; vv.w = src[3];
            *(float4*)(outb + (size_t)(m0 + row) * HH + ncol0 + c0 + c4 * 4) = vv;
        }
        __syncthreads();
    }

    if (wid == 0) TC_DEALLOC(tmem_base, 256);
#endif // HAS_TCGEN05
}

// ---------------------------------------------------------------------------
// Kernel 2: g projection (128 blocks x 256 threads, 1 row/thread)
// ---------------------------------------------------------------------------
__global__ __launch_bounds__(256)
void g_gemm_kernel(const float* __restrict__ x,
                   const float* __restrict__ Wg, const float* __restrict__ bg)
{
    __shared__ __align__(16) float Xs[16][260];
    __shared__ __align__(16) float Wgs[16][16];

    const int m0 = blockIdx.x * 256;
    const int tid = threadIdx.x;

    float acc[RR];
#pragma unroll
    for (int r = 0; r < RR; r++) acc[r] = 0.f;

    for (int d0 = 0; d0 < DD; d0 += 16) {
        {
            int d = tid >> 4, rr = tid & 15;
            Wgs[d][rr] = Wg[(size_t)rr * DD + d0 + d];
        }
#pragma unroll
        for (int p = 0; p < 4; p++) {
            int row = (tid >> 2) + p * 64;
            int dc  = (tid & 3) * 4;
            float4 v4 = *(const float4*)(x + (size_t)(m0 + row) * DD + d0 + dc);
            Xs[dc + 0][row] = v4.x;
            Xs[dc + 1][row] = v4.y;
            Xs[dc + 2][row] = v4.z;
            Xs[dc + 3][row] = v4.w;
        }
        __syncthreads();

#pragma unroll
        for (int d = 0; d < 16; d++) {
            float xv = Xs[d][tid];
#pragma unroll
            for (int r = 0; r < RR; r++)
                acc[r] = fmaf(xv, Wgs[d][r], acc[r]);
        }
        __syncthreads();
    }

    float* g0 = G_buf + (size_t)(m0 + tid) * RR;
#pragma unroll
    for (int r = 0; r < RR; r += 4) {
        float4 o0;
        o0.x = acc[r+0]+bg[r+0]; o0.y = acc[r+1]+bg[r+1];
        o0.z = acc[r+2]+bg[r+2]; o0.w = acc[r+3]+bg[r+3];
        *(float4*)(g0 + r) = o0;
    }
}

// ---------------------------------------------------------------------------
// Kernel 3: scan — R8 structure + packed fp32x2 FMA for both dot blocks.
// ---------------------------------------------------------------------------
__global__ __launch_bounds__(1024, 1)
void scan_kernel(const float* __restrict__ u_mat, const float* __restrict__ v_mat,
                 float* __restrict__ out)
{
    __shared__ __align__(16) float s_sm[HH];
    __shared__ __align__(16) float part[32][17];
    __shared__ __align__(16) float svg[16];
    __shared__ __align__(16) float g_sm[16];

    const int b    = blockIdx.x;
    const int tid  = threadIdx.x;
    const int wid  = tid >> 5;
    const int lane = tid & 31;
    const int r    = tid & 15;
    const int hg   = tid >> 4;

    // pre-pack v and u pairs: (2k low, 2k+1 high) to match memory pair order
    uint64_t vpk[8], upk[8];
#pragma unroll
    for (int k = 0; k < 8; k++) {
        float vlo = v_mat[(size_t)(hg * 16 + 2 * k)     * RR + r];
        float vhi = v_mat[(size_t)(hg * 16 + 2 * k + 1) * RR + r];
        vpk[k] = pk_f32x2(vlo, vhi);
        float ulo = u_mat[(size_t)tid * RR + 2 * k];
        float uhi = u_mat[(size_t)tid * RR + 2 * k + 1];
        upk[k] = pk_f32x2(ulo, uhi);
    }

    float s = 0.f;
    s_sm[tid] = 0.f;

    const size_t base = (size_t)b * SS;
    float a0 = A_buf[(base + 0) * HH + tid];
    float u0 = U_buf[(base + 0) * HH + tid];
    float g0 = G_buf[(base + 0) * RR + r];
    float a1 = A_buf[(base + 1) * HH + tid];
    float u1 = U_buf[(base + 1) * HH + tid];
    float g1 = G_buf[(base + 1) * RR + r];
    __syncthreads();

    for (int t = 0; t < SS; t++) {
        float a2 = 0.f, u2 = 0.f, g2 = 0.f;
        if (t + 2 < SS) {
            size_t o = base + t + 2;
            a2 = A_buf[o * HH + tid];
            u2 = U_buf[o * HH + tid];
            g2 = G_buf[o * RR + r];
        }
        if (tid < 16) g_sm[tid] = g0;

        // --- phase A: packed partial of (v^T s)[r] over 16 h's ---
        uint64_t accP0 = 0, accP1 = 0;   // packed (0,0)
        {
            const ulonglong2* sp = (const ulonglong2*)&s_sm[hg * 16];
            ulonglong2 m0 = sp[0], m1 = sp[1], m2 = sp[2], m3 = sp[3];
            accP0 = fma2(m0.x, vpk[0], accP0);
            accP1 = fma2(m0.y, vpk[1], accP1);
            accP0 = fma2(m1.x, vpk[2], accP0);
            accP1 = fma2(m1.y, vpk[3], accP1);
            accP0 = fma2(m2.x, vpk[4], accP0);
            accP1 = fma2(m2.y, vpk[5], accP1);
            accP0 = fma2(m3.x, vpk[6], accP0);
            accP1 = fma2(m3.y, vpk[7], accP1);
        }
        float acc = (pk_lo(accP0) + pk_hi(accP0)) + (pk_lo(accP1) + pk_hi(accP1));
        acc += __shfl_xor_sync(0xffffffffu, acc, 16);
        if (lane < 16) part[wid][lane] = acc;
        __syncthreads();   // bar1

        // --- phase B: warp w (w<16) reduces 32 partials for residual w ---
        if (wid < 16) {
            float pv = part[lane][wid];
            pv += __shfl_xor_sync(0xffffffffu, pv, 16);
            pv += __shfl_xor_sync(0xffffffffu, pv, 8);
            pv += __shfl_xor_sync(0xffffffffu, pv, 4);
            pv += __shfl_xor_sync(0xffffffffu, pv, 2);
            pv += __shfl_xor_sync(0xffffffffu, pv, 1);
            if (lane == 0) svg[wid] = g_sm[wid] * pv;
        }
        __syncthreads();   // bar2

        // --- phase C: packed dot svg·u[h,:] + elementwise update ---
        uint64_t dP0 = 0, dP1 = 0;
        {
            const ulonglong2* cp = (const ulonglong2*)&svg[0];
            ulonglong2 c0 = cp[0], c1 = cp[1], c2 = cp[2], c3 = cp[3];
            dP0 = fma2(c0.x, upk[0], dP0);
            dP1 = fma2(c0.y, upk[1], dP1);
            dP0 = fma2(c1.x, upk[2], dP0);
            dP1 = fma2(c1.y, upk[3], dP1);
            dP0 = fma2(c2.x, upk[4], dP0);
            dP1 = fma2(c2.y, upk[5], dP1);
            dP0 = fma2(c3.x, upk[6], dP0);
            dP1 = fma2(c3.y, upk[7], dP1);
        }
        s = fmaf(a0, s, u0);
        s += (pk_lo(dP0) + pk_hi(dP0)) + (pk_lo(dP1) + pk_hi(dP1));
        s_sm[tid] = s;
        a0 = a1; u0 = u1; g0 = g1;
        a1 = a2; u1 = u2; g1 = g2;
        __syncthreads();   // bar3
    }

    out[(size_t)b * HH + tid] = s;
}

// ---------------------------------------------------------------------------
extern "C" void kernel_launch(void* const* d_in, const int* in_sizes, int n_in,
                              void* d_out, int out_size)
{
    const float* x  = (const float*)d_in[0];
    const float* Wa = (const float*)d_in[1];
    const float* ba = (const float*)d_in[2];
    const float* Wg = (const float*)d_in[3];
    const float* bg = (const float*)d_in[4];
    const float* Wu = (const float*)d_in[5];
    const float* bu = (const float*)d_in[6];
    const float* u  = (const float*)d_in[7];
    const float* v  = (const float*)d_in[8];
    float* out = (float*)d_out;

    (void)in_sizes; (void)n_in; (void)out_size;

    cudaFuncSetAttribute(proj_gemm_tc, cudaFuncAttributeMaxDynamicSharedMemorySize, SMEM_TOTAL);

    convert_all_kernel<<<XBLKS + WBLKS, 256>>>(x, Wa, Wu);
    g_gemm_kernel<<<MTOT / 256, 256>>>(x, Wg, bg);
    proj_gemm_tc<<<dim3(NN2 / TN, MTOT / TM), 256, SMEM_TOTAL>>>(ba, bu);
    scan_kernel<<<BB, 1024>>>(u, v, out);
}

// round 14
// speedup vs baseline: 1.0030x; 1.0030x over previous
#include <cuda_runtime.h>
#include <cuda_bf16.h>
#include <cstdint>

#define BB 16
#define SS 2048
#define DD 1024
#define HH 1024
#define RR 16
#define MTOT (BB*SS)   // 32768
#define NN2 2048       // Wa||Wu stacked rows

#if defined(__CUDA_ARCH_FEAT_SM103_ALL) || defined(__CUDA_ARCH_FEAT_SM100_ALL)
#define HAS_TCGEN05 1
#elif defined(__CUDA_ARCH_SPECIFIC__)
#if (__CUDA_ARCH_SPECIFIC__ == 1030) || (__CUDA_ARCH_SPECIFIC__ == 1000)
#define HAS_TCGEN05 1
#else
#define HAS_TCGEN05 0
#endif
#else
#define HAS_TCGEN05 0
#endif

// Scratch
__device__ float A_buf[(size_t)BB*SS*HH];
__device__ float U_buf[(size_t)BB*SS*HH];
__device__ float G_buf[(size_t)BB*SS*RR];

__device__ __align__(16) __nv_bfloat16 Xhi[(size_t)MTOT*DD];
__device__ __align__(16) __nv_bfloat16 Xlo[(size_t)MTOT*DD];
__device__ __align__(16) __nv_bfloat16 Whi[(size_t)NN2*DD];
__device__ __align__(16) __nv_bfloat16 Wlo[(size_t)NN2*DD];

// ============================ helpers ============================
__device__ __forceinline__ uint32_t smem_u32(const void* p) {
    uint32_t a;
    asm("{ .reg .u64 t; cvta.to.shared.u64 t, %1; cvt.u32.u64 %0, t; }" : "=r"(a) : "l"(p));
    return a;
}
#define SWZ128(o) ((o) ^ (((o) >> 3) & 0x70))

__device__ __forceinline__ uint32_t pack_bf16x2(float lo, float hi) {
    uint32_t r;
    asm("cvt.rn.bf16x2.f32 %0, %1, %2;" : "=r"(r) : "f"(hi), "f"(lo));
    return r;
}

// packed fp32x2 helpers (HW FFMA2 on sm_100+/sm_103; scalar fallback for base pass)
__device__ __forceinline__ uint64_t pk_f32x2(float lo, float hi) {
    return ((uint64_t)__float_as_uint(hi) << 32) | (uint64_t)__float_as_uint(lo);
}
__device__ __forceinline__ float pk_lo(uint64_t p) { return __uint_as_float((uint32_t)p); }
__device__ __forceinline__ float pk_hi(uint64_t p) { return __uint_as_float((uint32_t)(p >> 32)); }

#if HAS_TCGEN05
__device__ __forceinline__ uint64_t fma2(uint64_t a, uint64_t b, uint64_t c) {
    uint64_t d;
    asm("fma.rn.f32x2 %0, %1, %2, %3;" : "=l"(d) : "l"(a), "l"(b), "l"(c));
    return d;
}
#else
__device__ __forceinline__ uint64_t fma2(uint64_t a, uint64_t b, uint64_t c) {
    return pk_f32x2(fmaf(pk_lo(a), pk_lo(b), pk_lo(c)),
                    fmaf(pk_hi(a), pk_hi(b), pk_hi(c)));
}
#endif

#if HAS_TCGEN05

__device__ __forceinline__ uint32_t elect_one() {
    uint32_t r;
    asm volatile("{ .reg .pred p; elect.sync _|p, 0xFFFFFFFF; selp.b32 %0, 1, 0, p; }" : "=r"(r));
    return r;
}

#define TC_ALLOC(smem_addr, ncols) \
    asm volatile("tcgen05.alloc.cta_group::1.sync.aligned.shared::cta.b32 [%0], %1;" \
                 :: "r"(smem_addr), "r"(ncols) : "memory")
#define TC_DEALLOC(tmem, ncols) \
    asm volatile("tcgen05.dealloc.cta_group::1.sync.aligned.b32 %0, %1;" :: "r"(tmem), "r"(ncols))
#define TC_COMMIT(mbar) \
    asm volatile("tcgen05.commit.cta_group::1.mbarrier::arrive::one.shared::cluster.b64 [%0];" \
                 :: "r"(mbar) : "memory")
#define TC_FENCE_AFTER()  asm volatile("tcgen05.fence::after_thread_sync;" ::: "memory")
#define TC_WAIT_LD()      asm volatile("tcgen05.wait::ld.sync.aligned;" ::: "memory")
#define FENCE_ASYNC_SHARED() asm volatile("fence.proxy.async.shared::cta;" ::: "memory")

#define CP_ASYNC16(dst, src) \
    asm volatile("cp.async.cg.shared.global [%0], [%1], 16;" :: "r"(dst), "l"(src) : "memory")
#define CP_COMMIT()  asm volatile("cp.async.commit_group;" ::: "memory")
#define CP_WAIT(n)   asm volatile("cp.async.wait_group %0;" :: "n"(n) : "memory")

#define MBAR_INIT(addr, cnt) \
    asm volatile("mbarrier.init.shared.b64 [%0], %1;" :: "r"(addr), "r"(cnt) : "memory")

#define MBAR_WAIT_PARITY(addr, parity) do { \
    uint32_t _mbar = (uint32_t)(addr); \
    uint32_t _par  = (uint32_t)(parity); \
    uint32_t _done; \
    asm volatile("{\n\t.reg .pred p;\n\t" \
        "mbarrier.try_wait.parity.acquire.cta.shared::cta.b64 p, [%1], %2;\n\t" \
        "selp.b32 %0, 1, 0, p;\n\t}" \
        : "=r"(_done) : "r"(_mbar), "r"(_par) : "memory"); \
    if (!_done) { \
        asm volatile("{\n\t.reg .pred P1;\n\t" \
            "WAIT_LOOP_%=:\n\t" \
            "mbarrier.try_wait.parity.acquire.cta.shared::cta.b64 P1, [%0], %1, 0x989680;\n\t" \
            "@P1 bra.uni WAIT_DONE_%=;\n\t" \
            "bra.uni WAIT_LOOP_%=;\n\t" \
            "WAIT_DONE_%=:\n\t}" \
            :: "r"(_mbar), "r"(_par) : "memory"); \
    } \
} while (0)

#define TC_LD_32X32B_X32(r, tmem_addr) \
    asm volatile( \
        "tcgen05.ld.sync.aligned.32x32b.x32.b32 " \
        "{%0, %1, %2, %3, %4, %5, %6, %7, " \
        " %8, %9, %10, %11, %12, %13, %14, %15, " \
        " %16, %17, %18, %19, %20, %21, %22, %23, " \
        " %24, %25, %26, %27, %28, %29, %30, %31}, [%32];" \
        : "=r"((r)[0]),  "=r"((r)[1]),  "=r"((r)[2]),  "=r"((r)[3]), \
          "=r"((r)[4]),  "=r"((r)[5]),  "=r"((r)[6]),  "=r"((r)[7]), \
          "=r"((r)[8]),  "=r"((r)[9]),  "=r"((r)[10]), "=r"((r)[11]), \
          "=r"((r)[12]), "=r"((r)[13]), "=r"((r)[14]), "=r"((r)[15]), \
          "=r"((r)[16]), "=r"((r)[17]), "=r"((r)[18]), "=r"((r)[19]), \
          "=r"((r)[20]), "=r"((r)[21]), "=r"((r)[22]), "=r"((r)[23]), \
          "=r"((r)[24]), "=r"((r)[25]), "=r"((r)[26]), "=r"((r)[27]), \
          "=r"((r)[28]), "=r"((r)[29]), "=r"((r)[30]), "=r"((r)[31]) \
        : "r"(tmem_addr))

// SW128 K-major smem descriptor (layout=2, version=1, SBO=64, LBO=1)
__device__ __forceinline__ uint64_t make_desc_sw128(uint32_t addr) {
    const uint64_t base = (uint64_t(2) << 61) | (uint64_t(1) << 46)
                        | (uint64_t(64) << 32) | (uint64_t(1) << 16);
    return base | ((uint64_t)(addr >> 4) & 0x3FFF);
}

__device__ __forceinline__ void mma_f16_ss(uint32_t d, uint64_t ad, uint64_t bd,
                                           uint32_t idesc, uint32_t en) {
    asm volatile(
        "{\n\t.reg .pred p;\n\t"
        "setp.ne.u32 p, %4, 0;\n\t"
        "tcgen05.mma.cta_group::1.kind::f16 [%0], %1, %2, %3, {%5,%5,%5,%5}, p;\n\t}"
        :: "r"(d), "l"(ad), "l"(bd), "r"(idesc), "r"(en), "r"(0u) : "memory");
}

#endif // HAS_TCGEN05

// ============================================================================
// Kernel 0: merged fp32 -> split-bf16 convert (X and W in one launch)
// ============================================================================
#define XBLKS ((MTOT * (DD/4)) / 256)   // 32768
#define WBLKS ((NN2  * (DD/4)) / 256)   // 2048

__global__ __launch_bounds__(256)
void convert_all_kernel(const float* __restrict__ x,
                        const float* __restrict__ Wa, const float* __restrict__ Wu)
{
    const float* src;
    __nv_bfloat16 *dhi, *dlo;
    size_t idx;
    if (blockIdx.x < XBLKS) {
        idx = (size_t)blockIdx.x * 256 + threadIdx.x;
        src = x + idx * 4;
        dhi = Xhi; dlo = Xlo;
    } else {
        idx = (size_t)(blockIdx.x - XBLKS) * 256 + threadIdx.x;
        size_t row = idx >> 8, col4 = idx & 255;
        src = (row < HH) ? (Wa + row * DD + col4 * 4) : (Wu + (row - HH) * DD + col4 * 4);
        dhi = Whi; dlo = Wlo;
    }
    float4 p = __ldg((const float4*)src);
    uint32_t w0 = __float_as_uint(p.x), w1 = __float_as_uint(p.y);
    uint32_t w2 = __float_as_uint(p.z), w3 = __float_as_uint(p.w);
    uint32_t h01 = __byte_perm(w0, w1, 0x7632);
    uint32_t h23 = __byte_perm(w2, w3, 0x7632);
    float l0 = p.x - __uint_as_float(w0 & 0xFFFF0000u);
    float l1 = p.y - __uint_as_float(w1 & 0xFFFF0000u);
    float l2 = p.z - __uint_as_float(w2 & 0xFFFF0000u);
    float l3 = p.w - __uint_as_float(w3 & 0xFFFF0000u);
    *(uint2*)(dhi + idx * 4) = make_uint2(h01, h23);
    *(uint2*)(dlo + idx * 4) = make_uint2(pack_bf16x2(l0, l1), pack_bf16x2(l2, l3));
}

// ============================================================================
// Kernel 1: tcgen05 split-bf16 projection GEMM (R6 known-good: 2-stage, KC=64)
// ============================================================================
#define TM 128
#define TN 256
#define KC 64
#define NCHUNK (DD / KC)     // 16

#define A_HI_OFF 0
#define A_LO_OFF 16384
#define B_HI_OFF 32768
#define B_LO_OFF 65536
#define STAGE_BYTES 98304
#define STAGE_BASE  1024
#define SMEM_TOTAL  (STAGE_BASE + 2 * STAGE_BYTES)   // 197632

__global__ __launch_bounds__(256, 1)
void proj_gemm_tc(const float* __restrict__ ba, const float* __restrict__ bu)
{
#if HAS_TCGEN05
    extern __shared__ char smem[];
    const uint32_t smb = smem_u32(smem);

    const uint32_t IDESC =
        (1u << 4) | (1u << 7) | (1u << 10) | ((TN / 8) << 17) | ((TM / 16) << 24);

    const int tid  = threadIdx.x;
    const int wid  = tid >> 5;
    const int lane = tid & 31;

    const int n0 = blockIdx.x * TN;
    const int m0 = blockIdx.y * TM;
    const bool isA = (n0 < HH);
    const int ncol0 = isA ? n0 : (n0 - HH);
    const float* bias = (isA ? ba : bu) + ncol0;
    float* outb = isA ? A_buf : U_buf;

    if (wid == 0) TC_ALLOC(smb + 0, 256);
    if (tid == 0) {
        MBAR_INIT(smb + 8, 1);
        MBAR_INIT(smb + 16, 1);
    }
    __syncthreads();
    uint32_t tmem_base;
    asm volatile("ld.shared.b32 %0, [%1];" : "=r"(tmem_base) : "r"(smb + 0));

    const uint32_t mb[2] = { smb + 8, smb + 16 };
    uint32_t ph[2] = { 0, 0 };

    for (int c = 0; c < NCHUNK; ++c) {
        const int st = c & 1;
        const uint32_t sb = smb + STAGE_BASE + st * STAGE_BYTES;
        const int kc0 = c * KC;

        if (c >= 2) { MBAR_WAIT_PARITY(mb[st], ph[st]); ph[st] ^= 1; }

        // A tiles: 128 rows x 64 bf16 (hi & lo)
        {
            const uint32_t aHi = sb + A_HI_OFF, aLo = sb + A_LO_OFF;
#pragma unroll
            for (int j = 0; j < 4; j++) {
                int u = tid + j * 256;              // 0..1023
                int row = u >> 3, cb = u & 7;
                uint32_t off = SWZ128((uint32_t)(row * 128 + cb * 16));
                const char* sH = (const char*)(Xhi + (size_t)(m0 + row) * DD + kc0) + cb * 16;
                const char* sL = (const char*)(Xlo + (size_t)(m0 + row) * DD + kc0) + cb * 16;
                CP_ASYNC16(aHi + off, sH);
                CP_ASYNC16(aLo + off, sL);
            }
        }
        // B tiles: 256 rows x 64 bf16 (hi & lo)
        {
            const uint32_t bHi = sb + B_HI_OFF, bLo = sb + B_LO_OFF;
#pragma unroll
            for (int j = 0; j < 8; j++) {
                int u = tid + j * 256;              // 0..2047
                int row = u >> 3, cb = u & 7;
                uint32_t off = SWZ128((uint32_t)(row * 128 + cb * 16));
                const char* sH = (const char*)(Whi + (size_t)(n0 + row) * DD + kc0) + cb * 16;
                const char* sL = (const char*)(Wlo + (size_t)(n0 + row) * DD + kc0) + cb * 16;
                CP_ASYNC16(bHi + off, sH);
                CP_ASYNC16(bLo + off, sL);
            }
        }
        CP_COMMIT();
        CP_WAIT(0);
        __syncthreads();

        if (wid == 0) {
            FENCE_ASYNC_SHARED();
            if (elect_one()) {
                uint64_t dAhi = make_desc_sw128(sb + A_HI_OFF);
                uint64_t dAlo = make_desc_sw128(sb + A_LO_OFF);
                uint64_t dBhi = make_desc_sw128(sb + B_HI_OFF);
                uint64_t dBlo = make_desc_sw128(sb + B_LO_OFF);
#pragma unroll
                for (int k = 0; k < 4; k++) {
                    uint32_t en0 = (c > 0 || k > 0) ? 1u : 0u;
                    mma_f16_ss(tmem_base, dAhi + k * 2, dBhi + k * 2, IDESC, en0);
                    mma_f16_ss(tmem_base, dAhi + k * 2, dBlo + k * 2, IDESC, 1u);
                    mma_f16_ss(tmem_base, dAlo + k * 2, dBhi + k * 2, IDESC, 1u);
                }
                TC_COMMIT(mb[st]);
            }
        }
    }

    MBAR_WAIT_PARITY(mb[0], ph[0]);
    MBAR_WAIT_PARITY(mb[1], ph[1]);
    TC_FENCE_AFTER();
    __syncthreads();

    // epilogue
    float* stg = (float*)(smem + STAGE_BASE);
    const int half = wid >> 2;
    const int subw = wid & 3;
    const int rowl = subw * 32 + lane;

    for (int slab = 0; slab < 4; ++slab) {
        const int c0 = slab * 64;
        uint32_t regs[32];
        TC_LD_32X32B_X32(regs, tmem_base + c0 + half * 32);
        TC_WAIT_LD();
#pragma unroll
        for (int j = 0; j < 32; j++) {
            int n = c0 + half * 32 + j;
            float val = __uint_as_float(regs[j]) + __ldg(&bias[n]);
            if (isA) val = 1.f / (1.f + __expf(-val));
            stg[rowl * 65 + half * 32 + j] = val;
        }
        __syncthreads();
#pragma unroll
        for (int i = 0; i < 8; i++) {
            int idx = tid + i * 256;
            int row = idx >> 4, c4 = idx & 15;
            const float* src = &stg[row * 65 + c4 * 4];
            float4 vv;
            vv.x = src[0]; vv.y = src[1]; vv.z = src[2]; vv.w = src[3];
            *(float4*)(outb + (size_t)(m0 + row) * HH + ncol0 + c0 + c4 * 4) = vv;
        }
        __syncthreads();
    }

    if (wid == 0) TC_DEALLOC(tmem_base, 256);
#endif // HAS_TCGEN05
}

// ---------------------------------------------------------------------------
// Kernel 2: g projection (128 blocks x 256 threads, 1 row/thread)
// ---------------------------------------------------------------------------
__global__ __launch_bounds__(256)
void g_gemm_kernel(const float* __restrict__ x,
                   const float* __restrict__ Wg, const float* __restrict__ bg)
{
    __shared__ __align__(16) float Xs[16][260];
    __shared__ __align__(16) float Wgs[16][16];

    const int m0 = blockIdx.x * 256;
    const int tid = threadIdx.x;

    float acc[RR];
#pragma unroll
    for (int r = 0; r < RR; r++) acc[r] = 0.f;

    for (int d0 = 0; d0 < DD; d0 += 16) {
        {
            int d = tid >> 4, rr = tid & 15;
            Wgs[d][rr] = Wg[(size_t)rr * DD + d0 + d];
        }
#pragma unroll
        for (int p = 0; p < 4; p++) {
            int row = (tid >> 2) + p * 64;
            int dc  = (tid & 3) * 4;
            float4 v4 = *(const float4*)(x + (size_t)(m0 + row) * DD + d0 + dc);
            Xs[dc + 0][row] = v4.x;
            Xs[dc + 1][row] = v4.y;
            Xs[dc + 2][row] = v4.z;
            Xs[dc + 3][row] = v4.w;
        }
        __syncthreads();

#pragma unroll
        for (int d = 0; d < 16; d++) {
            float xv = Xs[d][tid];
#pragma unroll
            for (int r = 0; r < RR; r++)
                acc[r] = fmaf(xv, Wgs[d][r], acc[r]);
        }
        __syncthreads();
    }

    float* g0 = G_buf + (size_t)(m0 + tid) * RR;
#pragma unroll
    for (int r = 0; r < RR; r += 4) {
        float4 o0;
        o0.x = acc[r+0]+bg[r+0]; o0.y = acc[r+1]+bg[r+1];
        o0.z = acc[r+2]+bg[r+2]; o0.w = acc[r+3]+bg[r+3];
        *(float4*)(g0 + r) = o0;
    }
}

// ---------------------------------------------------------------------------
// Kernel 3: scan — R8 structure + packed fp32x2 FMA for both dot blocks.
// ---------------------------------------------------------------------------
__global__ __launch_bounds__(1024, 1)
void scan_kernel(const float* __restrict__ u_mat, const float* __restrict__ v_mat,
                 float* __restrict__ out)
{
    __shared__ __align__(16) float s_sm[HH];
    __shared__ __align__(16) float part[32][17];
    __shared__ __align__(16) float svg[16];
    __shared__ __align__(16) float g_sm[16];

    const int b    = blockIdx.x;
    const int tid  = threadIdx.x;
    const int wid  = tid >> 5;
    const int lane = tid & 31;
    const int r    = tid & 15;
    const int hg   = tid >> 4;

    // pre-pack v and u pairs: (2k low, 2k+1 high) to match memory pair order
    uint64_t vpk[8], upk[8];
#pragma unroll
    for (int k = 0; k < 8; k++) {
        float vlo = v_mat[(size_t)(hg * 16 + 2 * k)     * RR + r];
        float vhi = v_mat[(size_t)(hg * 16 + 2 * k + 1) * RR + r];
        vpk[k] = pk_f32x2(vlo, vhi);
        float ulo = u_mat[(size_t)tid * RR + 2 * k];
        float uhi = u_mat[(size_t)tid * RR + 2 * k + 1];
        upk[k] = pk_f32x2(ulo, uhi);
    }

    float s = 0.f;
    s_sm[tid] = 0.f;

    const size_t base = (size_t)b * SS;
    float a0 = A_buf[(base + 0) * HH + tid];
    float u0 = U_buf[(base + 0) * HH + tid];
    float g0 = G_buf[(base + 0) * RR + r];
    float a1 = A_buf[(base + 1) * HH + tid];
    float u1 = U_buf[(base + 1) * HH + tid];
    float g1 = G_buf[(base + 1) * RR + r];
    __syncthreads();

    for (int t = 0; t < SS; t++) {
        float a2 = 0.f, u2 = 0.f, g2 = 0.f;
        if (t + 2 < SS) {
            size_t o = base + t + 2;
            a2 = A_buf[o * HH + tid];
            u2 = U_buf[o * HH + tid];
            g2 = G_buf[o * RR + r];
        }
        if (tid < 16) g_sm[tid] = g0;

        // --- phase A: packed partial of (v^T s)[r] over 16 h's ---
        uint64_t accP0 = 0, accP1 = 0;   // packed (0,0)
        {
            const ulonglong2* sp = (const ulonglong2*)&s_sm[hg * 16];
            ulonglong2 m0 = sp[0], m1 = sp[1], m2 = sp[2], m3 = sp[3];
            accP0 = fma2(m0.x, vpk[0], accP0);
            accP1 = fma2(m0.y, vpk[1], accP1);
            accP0 = fma2(m1.x, vpk[2], accP0);
            accP1 = fma2(m1.y, vpk[3], accP1);
            accP0 = fma2(m2.x, vpk[4], accP0);
            accP1 = fma2(m2.y, vpk[5], accP1);
            accP0 = fma2(m3.x, vpk[6], accP0);
            accP1 = fma2(m3.y, vpk[7], accP1);
        }
        float acc = (pk_lo(accP0) + pk_hi(accP0)) + (pk_lo(accP1) + pk_hi(accP1));
        acc += __shfl_xor_sync(0xffffffffu, acc, 16);
        if (lane < 16) part[wid][lane] = acc;
        __syncthreads();   // bar1

        // --- phase B: warp w (w<16) reduces 32 partials for residual w ---
        if (wid < 16) {
            float pv = part[lane][wid];
            pv += __shfl_xor_sync(0xffffffffu, pv, 16);
            pv += __shfl_xor_sync(0xffffffffu, pv, 8);
            pv += __shfl_xor_sync(0xffffffffu, pv, 4);
            pv += __shfl_xor_sync(0xffffffffu, pv, 2);
            pv += __shfl_xor_sync(0xffffffffu, pv, 1);
            if (lane == 0) svg[wid] = g_sm[wid] * pv;
        }
        __syncthreads();   // bar2

        // --- phase C: packed dot svg·u[h,:] + elementwise update ---
        uint64_t dP0 = 0, dP1 = 0;
        {
            const ulonglong2* cp = (const ulonglong2*)&svg[0];
            ulonglong2 c0 = cp[0], c1 = cp[1], c2 = cp[2], c3 = cp[3];
            dP0 = fma2(c0.x, upk[0], dP0);
            dP1 = fma2(c0.y, upk[1], dP1);
            dP0 = fma2(c1.x, upk[2], dP0);
            dP1 = fma2(c1.y, upk[3], dP1);
            dP0 = fma2(c2.x, upk[4], dP0);
            dP1 = fma2(c2.y, upk[5], dP1);
            dP0 = fma2(c3.x, upk[6], dP0);
            dP1 = fma2(c3.y, upk[7], dP1);
        }
        s = fmaf(a0, s, u0);
        s += (pk_lo(dP0) + pk_hi(dP0)) + (pk_lo(dP1) + pk_hi(dP1));
        s_sm[tid] = s;
        a0 = a1; u0 = u1; g0 = g1;
        a1 = a2; u1 = u2; g1 = g2;
        __syncthreads();   // bar3
    }

    out[(size_t)b * HH + tid] = s;
}

// ---------------------------------------------------------------------------
extern "C" void kernel_launch(void* const* d_in, const int* in_sizes, int n_in,
                              void* d_out, int out_size)
{
    const float* x  = (const float*)d_in[0];
    const float* Wa = (const float*)d_in[1];
    const float* ba = (const float*)d_in[2];
    const float* Wg = (const float*)d_in[3];
    const float* bg = (const float*)d_in[4];
    const float* Wu = (const float*)d_in[5];
    const float* bu = (const float*)d_in[6];
    const float* u  = (const float*)d_in[7];
    const float* v  = (const float*)d_in[8];
    float* out = (float*)d_out;

    (void)in_sizes; (void)n_in; (void)out_size;

    cudaFuncSetAttribute(proj_gemm_tc, cudaFuncAttributeMaxDynamicSharedMemorySize, SMEM_TOTAL);

    convert_all_kernel<<<XBLKS + WBLKS, 256>>>(x, Wa, Wu);
    g_gemm_kernel<<<MTOT / 256, 256>>>(x, Wg, bg);
    proj_gemm_tc<<<dim3(NN2 / TN, MTOT / TM), 256, SMEM_TOTAL>>>(ba, bu);
    scan_kernel<<<BB, 1024>>>(u, v, out);
}